// round 6
// baseline (speedup 1.0000x reference)
#include <cuda_runtime.h>
#include <cuda_bf16.h>
#include <math.h>
#include <stdint.h>

// Problem constants
#define Tn 16384            // B*N tokens
#define Dd 768
#define Ff 3072
#define Ee 16
#define CAPc 160
#define Bbat 8
#define Nseq 2048
#define LCAP 320            // max list entries per (b,e)

// Output layout (float32, concatenated in reference return order)
#define OFF_AUX    12582912
#define OFF_BAL    12582913
#define OFF_ZL     12582914
#define OFF_LOGITS 12582915ll
#define OFF_ENERGY 12845059ll
#define OFF_GIDX   12861443ll

// ---------------- scratch (device globals; no runtime allocation) ----------------
__device__ float g_wi[(size_t)Tn * Dd];               // RMS-normed input (fp32)
__device__ float g_h [(size_t)Tn * Ff];               // h (fp32)
__device__ __nv_bfloat16 g_A1[(size_t)Tn * 2 * Dd];   // [wi_hi | wi_lo]
__device__ __nv_bfloat16 g_B1[(size_t)Ff * 2 * Dd];   // [Wi_hi | Wi_lo]
__device__ __nv_bfloat16 g_A2[(size_t)Tn * 2 * Ff];   // [h_hi  | h_lo]
__device__ __nv_bfloat16 g_B2[(size_t)Dd * 2 * Ff];   // [Wo_hi | Wo_lo]
__device__ int   g_e  [2 * Tn];
__device__ float g_gate[2 * Tn];
__device__ float g_gp  [2 * Tn];                      // gate after drop (0 if dropped)
__device__ int   g_sh1 [Tn];
__device__ float g_dp[Bbat * Ee];
__device__ float g_d1[Bbat * Ee];
__device__ float g_zl;
// per-(b,e) alive token lists
__device__ int   g_ltok[Bbat * Ee * LCAP];
__device__ float g_lg  [Bbat * Ee * LCAP];
__device__ int   g_lcnt[Bbat * Ee];

// ---------------- PTX helpers (sm_100-safe) ----------------
__device__ __forceinline__ uint32_t s2u(const void* p) {
    uint32_t a;
    asm("{ .reg .u64 t; cvta.to.shared.u64 t, %1; cvt.u32.u64 %0, t; }" : "=r"(a) : "l"(p));
    return a;
}
__device__ __forceinline__ void cpa16(uint32_t s, const void* g) {
    asm volatile("cp.async.cg.shared.global [%0], [%1], 16;\n" :: "r"(s), "l"(g));
}
#define CPA_COMMIT() asm volatile("cp.async.commit_group;\n" ::: "memory")
#define CPA_WAIT2()  asm volatile("cp.async.wait_group 2;\n" ::: "memory")

__device__ __forceinline__ void ldsm4(uint32_t* r, uint32_t a) {
    asm volatile("ldmatrix.sync.aligned.m8n8.x4.shared.b16 {%0,%1,%2,%3}, [%4];"
                 : "=r"(r[0]), "=r"(r[1]), "=r"(r[2]), "=r"(r[3]) : "r"(a));
}
__device__ __forceinline__ void mma16816(float* c, const uint32_t* a, uint32_t b0, uint32_t b1) {
    asm volatile("mma.sync.aligned.m16n8k16.row.col.f32.bf16.bf16.f32 "
                 "{%0,%1,%2,%3}, {%4,%5,%6,%7}, {%8,%9}, {%0,%1,%2,%3};"
                 : "+f"(c[0]), "+f"(c[1]), "+f"(c[2]), "+f"(c[3])
                 : "r"(a[0]), "r"(a[1]), "r"(a[2]), "r"(a[3]), "r"(b0), "r"(b1));
}

#define SWZ(o) ((o) ^ (((o) >> 3) & 0x70))

// GEMM smem: A stages [128][64]bf16 = 16KB (x4), B stages [256][64]bf16 = 32KB (x4)
#define SM_A(s) ((s) * 16384)
#define SM_B(s) (65536 + (s) * 32768)
#define SMEM_GEMM 196608

// fused kernels smem: u[320*16] + buf[49152] floats
#define FUSED_SMEM 217088

// ---------------- stage loader: chunk c of the 3-term schedule over 2-term storage ----
__device__ __forceinline__ void load_stage(uint32_t sb, int s,
                                           const __nv_bfloat16* __restrict__ A,
                                           const __nv_bfloat16* __restrict__ B,
                                           int bm, int bn, int c, int cpt, int K, int tid) {
    int t = c / cpt;
    int kc = (c - t * cpt) * 64;
    int aoff = (t == 1) ? K : 0;   // A terms: hi, lo, hi
    int boff = (t == 2) ? K : 0;   // B terms: hi, hi, lo
    const int K2 = 2 * K;
    #pragma unroll
    for (int j = 0; j < 2; j++) {
        int idx = tid + 512 * j, row = idx >> 3, seg = idx & 7;
        cpa16(sb + SM_A(s) + SWZ(row * 128 + seg * 16),
              A + (size_t)(bm + row) * K2 + aoff + kc + seg * 8);
    }
    #pragma unroll
    for (int j = 0; j < 4; j++) {
        int idx = tid + 512 * j, row = idx >> 3, seg = idx & 7;
        cpa16(sb + SM_B(s) + SWZ(row * 128 + seg * 16),
              B + (size_t)(bn + row) * K2 + boff + kc + seg * 8);
    }
}

// ---------------- mma.sync split-bf16 GEMM with fused epilogues ----------------
// Tile 128(M) x 256(N), K-chunk 64, 4-stage cp.async pipeline, 512 threads.
// mode 1: C = relu(z) + gs*z         (GEMM1 -> h)
// mode 2: C = x + (1+gs)*z           (GEMM2 -> out)
__global__ __launch_bounds__(512, 1)
void k_tc_gemm(const __nv_bfloat16* __restrict__ A, const __nv_bfloat16* __restrict__ B,
               float* __restrict__ C, int Ncols, int K, int cpt, int KI,
               int mode, const float* __restrict__ x) {
    extern __shared__ char smem[];
    const uint32_t sb = s2u(smem);
    const int tid = threadIdx.x;
    const int wid = tid >> 5;
    const int lane = tid & 31;
    const int warp_m = wid & 3;
    const int warp_n = wid >> 2;
    const int bm = blockIdx.y * 128;
    const int bn = blockIdx.x * 256;

    float acc[2][8][4];
    #pragma unroll
    for (int i = 0; i < 2; i++)
        #pragma unroll
        for (int j = 0; j < 8; j++)
            #pragma unroll
            for (int q = 0; q < 4; q++) acc[i][j][q] = 0.f;

    // prologue: stages 0,1,2
    #pragma unroll
    for (int c = 0; c < 3; c++) {
        load_stage(sb, c, A, B, bm, bn, c, cpt, K, tid);
        CPA_COMMIT();
    }

    for (int i = 0; i < KI; i++) {
        const int si = i & 3;
        CPA_WAIT2();
        __syncthreads();

        const int j = i + 3;
        if (j < KI) load_stage(sb, j & 3, A, B, bm, bn, j, cpt, K, tid);
        CPA_COMMIT();

        const uint32_t sa = sb + SM_A(si);
        const uint32_t sB = sb + SM_B(si);
        #pragma unroll
        for (int ks = 0; ks < 4; ks++) {
            uint32_t a[2][4];
            #pragma unroll
            for (int mt = 0; mt < 2; mt++) {
                int row = warp_m * 32 + mt * 16 + (lane & 15);
                ldsm4(a[mt], sa + SWZ(row * 128 + ks * 32 + ((lane >> 4) << 4)));
            }
            uint32_t b[4][4];
            #pragma unroll
            for (int g = 0; g < 4; g++) {
                int nr = warp_n * 64 + g * 16 + ((lane >> 4) << 3) + (lane & 7);
                ldsm4(b[g], sB + SWZ(nr * 128 + ks * 32 + (((lane >> 3) & 1) << 4)));
            }
            #pragma unroll
            for (int mt = 0; mt < 2; mt++)
                #pragma unroll
                for (int nt = 0; nt < 8; nt++) {
                    int g = nt >> 1, hf = (nt & 1) << 1;
                    mma16816(acc[mt][nt], a[mt], b[g][hf], b[g][hf + 1]);
                }
        }
        __syncthreads();
    }

    // fused epilogue
    #pragma unroll
    for (int mt = 0; mt < 2; mt++) {
        int r0 = bm + warp_m * 32 + mt * 16 + (lane >> 2);
        float gs0 = g_gp[r0] + g_gp[Tn + r0];
        float gs8 = g_gp[r0 + 8] + g_gp[Tn + r0 + 8];
        #pragma unroll
        for (int nt = 0; nt < 8; nt++) {
            int col = bn + warp_n * 64 + nt * 8 + (lane & 3) * 2;
            float v0 = acc[mt][nt][0], v1 = acc[mt][nt][1];
            float v2 = acc[mt][nt][2], v3 = acc[mt][nt][3];
            float* c0 = C + (size_t)r0 * Ncols + col;
            float* c8 = C + (size_t)(r0 + 8) * Ncols + col;
            if (mode == 1) {
                *(float2*)c0 = make_float2(fmaxf(v0, 0.f) + gs0 * v0, fmaxf(v1, 0.f) + gs0 * v1);
                *(float2*)c8 = make_float2(fmaxf(v2, 0.f) + gs8 * v2, fmaxf(v3, 0.f) + gs8 * v3);
            } else {
                float2 x0 = *(const float2*)(x + (size_t)r0 * Ncols + col);
                float2 x8 = *(const float2*)(x + (size_t)(r0 + 8) * Ncols + col);
                *(float2*)c0 = make_float2(x0.x + (1.f + gs0) * v0, x0.y + (1.f + gs0) * v1);
                *(float2*)c8 = make_float2(x8.x + (1.f + gs8) * v2, x8.y + (1.f + gs8) * v3);
            }
        }
    }
}

// ---------------- init ----------------
__global__ void k_init() {
    int i = threadIdx.x;
    if (i < Bbat * Ee) g_dp[i] = 0.f;
    if (i == 0) g_zl = 0.f;
}

// ---------------- RMS norm (+ split-bf16 A1 build, [hi|lo]) ----------------
__global__ __launch_bounds__(256) void k_rms(const float* __restrict__ x,
                                             const float* __restrict__ lnw) {
    int t = blockIdx.x;
    const float* xr = x + (size_t)t * Dd;
    float s = 0.f;
    for (int d = threadIdx.x; d < Dd; d += 256) { float v = xr[d]; s += v * v; }
    __shared__ float red[256];
    red[threadIdx.x] = s; __syncthreads();
    for (int o = 128; o > 0; o >>= 1) {
        if (threadIdx.x < o) red[threadIdx.x] += red[threadIdx.x + o];
        __syncthreads();
    }
    float inv = rsqrtf(red[0] / (float)Dd + 1e-6f);
    __nv_bfloat16* a1 = g_A1 + (size_t)t * 2 * Dd;
    for (int d = threadIdx.x; d < Dd; d += 256) {
        float v = xr[d] * inv * lnw[d];
        g_wi[(size_t)t * Dd + d] = v;
        __nv_bfloat16 hi = __float2bfloat16(v);
        __nv_bfloat16 lo = __float2bfloat16(v - __bfloat162float(hi));
        a1[d] = hi; a1[Dd + d] = lo;
    }
}

// ---------------- weight splits [hi|lo] ----------------
__global__ __launch_bounds__(256) void k_splitB1(const float* __restrict__ Wi) {
    int r = blockIdx.x;
    __nv_bfloat16* b1 = g_B1 + (size_t)r * 2 * Dd;
    const float* wr = Wi + (size_t)r * Dd;
    for (int d = threadIdx.x; d < Dd; d += 256) {
        float v = wr[d];
        __nv_bfloat16 hi = __float2bfloat16(v);
        __nv_bfloat16 lo = __float2bfloat16(v - __bfloat162float(hi));
        b1[d] = hi; b1[Dd + d] = lo;
    }
}
__global__ __launch_bounds__(256) void k_splitB2(const float* __restrict__ Wo) {
    int r = blockIdx.x;
    __nv_bfloat16* b2 = g_B2 + (size_t)r * 2 * Ff;
    const float* wr = Wo + (size_t)r * Ff;
    for (int d = threadIdx.x; d < Ff; d += 256) {
        float v = wr[d];
        __nv_bfloat16 hi = __float2bfloat16(v);
        __nv_bfloat16 lo = __float2bfloat16(v - __bfloat162float(hi));
        b2[d] = hi; b2[Ff + d] = lo;
    }
}

// ---------------- logits = wi_in @ Wg^T ----------------
__global__ __launch_bounds__(256) void k_logits(const float* __restrict__ Wg,
                                                float* __restrict__ out) {
    __shared__ float sWg[Dd * 16];
    for (int i = threadIdx.x; i < Dd * 16; i += 256) {
        int e = i / Dd, d = i % Dd;
        sWg[d * 16 + e] = Wg[i];
    }
    __syncthreads();
    int tok = blockIdx.x * 16 + (threadIdx.x >> 4);
    int e = threadIdx.x & 15;
    const float* wr = g_wi + (size_t)tok * Dd;
    float s = 0.f;
    #pragma unroll 4
    for (int d = 0; d < Dd; d++) s += wr[d] * sWg[d * 16 + e];
    out[OFF_LOGITS + (size_t)tok * 16 + e] = s;
}

// ---------------- softmax / top2 / gates / aux partials ----------------
__global__ __launch_bounds__(256) void k_gate(const float* __restrict__ rp,
                                              float* __restrict__ out) {
    int t = blockIdx.x * 256 + threadIdx.x;
    const float* lg = out + OFF_LOGITS + (size_t)t * 16;
    float l[16];
    float mx = -1e30f;
    #pragma unroll
    for (int e = 0; e < 16; e++) { l[e] = lg[e]; mx = fmaxf(mx, l[e]); }
    float se = 0.f;
    #pragma unroll
    for (int e = 0; e < 16; e++) se += expf(l[e] - mx);
    float lse = mx + logf(se);
    out[OFF_ENERGY + t] = -lse;

    int e0 = 0; float b0 = l[0];
    #pragma unroll
    for (int e = 1; e < 16; e++) if (l[e] > b0) { b0 = l[e]; e0 = e; }
    int e1 = -1; float b1 = -1e30f;
    #pragma unroll
    for (int e = 0; e < 16; e++) if (e != e0 && l[e] > b1) { b1 = l[e]; e1 = e; }
    float v0 = expf(b0 - lse), v1 = expf(b1 - lse);
    float den = v0 + v1; if (den < 1e-9f) den = 1e-9f;
    float G0 = v0 / den, G1 = v1 / den;
    g_e[t] = e0; g_e[Tn + t] = e1;
    g_gate[t] = G0; g_gate[Tn + t] = G1;
    g_sh1[t] = (rp[Tn + t] < G1 * 5.0f) ? 1 : 0;

    __shared__ float sdp[16];
    __shared__ float szl;
    if (threadIdx.x < 16) sdp[threadIdx.x] = 0.f;
    if (threadIdx.x == 0) szl = 0.f;
    __syncthreads();
    #pragma unroll
    for (int e = 0; e < 16; e++) atomicAdd(&sdp[e], expf(l[e] - lse));
    atomicAdd(&szl, lse * lse);
    __syncthreads();
    int b = t >> 11;
    if (threadIdx.x < 16) atomicAdd(&g_dp[b * 16 + threadIdx.x], sdp[threadIdx.x]);
    if (threadIdx.x == 0) atomicAdd(&g_zl, szl);
}

// ---------------- capacity scan + alive-list build ----------------
__global__ void k_scan(float* __restrict__ out) {
    if (threadIdx.x != 0) return;
    int b = blockIdx.x;
    int base = b * Nseq;
    int c0[16], cl[16];
    #pragma unroll
    for (int e = 0; e < 16; e++) { c0[e] = 0; cl[e] = 0; }
    for (int n = 0; n < Nseq; n++) {
        int t = base + n;
        int e = g_e[t];
        int pos = c0[e]++;
        bool s = pos < CAPc;
        g_gp[t] = s ? g_gate[t] : 0.f;
        out[OFF_GIDX + t] = s ? (float)e : 0.f;
        if (s) {
            int li = (b * 16 + e) * LCAP + cl[e];
            g_ltok[li] = t; g_lg[li] = g_gate[t];
            cl[e]++;
        }
    }
    int c1[16];
    #pragma unroll
    for (int e = 0; e < 16; e++) {
        int sv = c0[e] < CAPc ? c0[e] : CAPc;
        g_d1[b * 16 + e] = (float)sv / (float)Nseq;
        c1[e] = sv;
    }
    for (int n = 0; n < Nseq; n++) {
        int t = base + n;
        if (g_sh1[t]) {
            int e = g_e[Tn + t];
            int pos = c1[e]++;
            bool s = pos < CAPc;
            g_gp[Tn + t] = s ? g_gate[Tn + t] : 0.f;
            out[OFF_GIDX + Tn + t] = s ? (float)e : 0.f;
            if (s) {
                int li = (b * 16 + e) * LCAP + cl[e];
                g_ltok[li] = t; g_lg[li] = g_gate[Tn + t];
                cl[e]++;
            }
        } else {
            g_gp[Tn + t] = 0.f;
            out[OFF_GIDX + Tn + t] = 0.f;
        }
    }
    #pragma unroll
    for (int e = 0; e < 16; e++) g_lcnt[b * 16 + e] = cl[e];
}

// ---------------- aux scalars ----------------
__global__ void k_aux(float* __restrict__ out) {
    __shared__ float red[128];
    int i = threadIdx.x;
    red[i] = (g_dp[i] / (float)Nseq) * g_d1[i];
    __syncthreads();
    for (int o = 64; o > 0; o >>= 1) {
        if (i < o) red[i] += red[i + o];
        __syncthreads();
    }
    if (i == 0) {
        float bal = red[0] * 2.0f;
        float zl = g_zl / (float)Tn;
        out[OFF_BAL] = bal;
        out[OFF_ZL] = zl;
        out[OFF_AUX] = 0.01f * bal + 0.01f * zl;
    }
}

// ---------------- fused wi-path LoRA: u = wi@Ai[e], h += 2g*(u@Bi[e]) ----------------
// one block per (b,e); smem: su[320*16] + buf[49152]
__global__ __launch_bounds__(256) void k_fused1(const float* __restrict__ Ai,
                                                const float* __restrict__ Bi) {
    extern __shared__ float sm[];
    float* su = sm;
    float* buf = sm + LCAP * 16;
    int bi = blockIdx.x;
    int e = bi & 15;
    int cnt = g_lcnt[bi];
    int tid = threadIdx.x, lane = tid & 31, wid = tid >> 5;

    // phase 1: Ai_e -> smem (768x16), compute u per entry
    for (int i = tid; i < Dd * 16; i += 256) buf[i] = Ai[(size_t)e * Dd * 16 + i];
    __syncthreads();
    for (int i = wid; i < cnt; i += 8) {
        int t = g_ltok[bi * LCAP + i];
        int r = lane & 15, half = lane >> 4;
        const float* wr = g_wi + (size_t)t * Dd + half * 384;
        float acc = 0.f;
        #pragma unroll 4
        for (int d = 0; d < 384; d += 4) {
            float4 v = *(const float4*)(wr + d);
            int db = (half * 384 + d) * 16 + r;
            acc += v.x * buf[db] + v.y * buf[db + 16] + v.z * buf[db + 32] + v.w * buf[db + 48];
        }
        acc += __shfl_xor_sync(0xffffffffu, acc, 16);
        if (half == 0) su[i * 16 + r] = acc;
    }
    __syncthreads();

    // phase 2: Bi_e -> smem (16x3072), add deltas (warp handles 4 entries)
    for (int i = tid; i < 16 * Ff; i += 256) buf[i] = Bi[(size_t)e * 16 * Ff + i];
    __syncthreads();
    for (int g0i = wid * 4; g0i < cnt; g0i += 32) {
        int nt = cnt - g0i; if (nt > 4) nt = 4;
        float u[4][16]; float gg[4]; int tt[4];
        #pragma unroll
        for (int j = 0; j < 4; j++) {
            int i2 = g0i + (j < nt ? j : 0);
            tt[j] = g_ltok[bi * LCAP + i2];
            gg[j] = (j < nt) ? 2.f * g_lg[bi * LCAP + i2] : 0.f;
            #pragma unroll
            for (int r = 0; r < 16; r++) u[j][r] = su[i2 * 16 + r];
        }
        for (int f = lane; f < Ff; f += 32) {
            float bv[16];
            #pragma unroll
            for (int r = 0; r < 16; r++) bv[r] = buf[r * Ff + f];
            #pragma unroll
            for (int j = 0; j < 4; j++) {
                float d = 0.f;
                #pragma unroll
                for (int r = 0; r < 16; r++) d += u[j][r] * bv[r];
                if (gg[j] != 0.f) atomicAdd(g_h + (size_t)tt[j] * Ff + f, gg[j] * d);
            }
        }
    }
}

// ---------------- A2 build from final h ([hi|lo]) ----------------
__global__ __launch_bounds__(256) void k_hC() {
    int t = blockIdx.x;
    const float* hr = g_h + (size_t)t * Ff;
    __nv_bfloat16* a2 = g_A2 + (size_t)t * 2 * Ff;
    for (int f = threadIdx.x; f < Ff; f += 256) {
        float v = hr[f];
        __nv_bfloat16 hi = __float2bfloat16(v);
        __nv_bfloat16 lo = __float2bfloat16(v - __bfloat162float(hi));
        a2[f] = hi; a2[Ff + f] = lo;
    }
}

// ---------------- fused wo-path LoRA: u2 = h@Ao[e], out += 2g*(u2@Bo[e]) ----------------
__global__ __launch_bounds__(256) void k_fused2(const float* __restrict__ Ao,
                                                const float* __restrict__ Bo,
                                                float* __restrict__ out) {
    extern __shared__ float sm[];
    float* su = sm;
    float* buf = sm + LCAP * 16;
    int bi = blockIdx.x;
    int e = bi & 15;
    int cnt = g_lcnt[bi];
    int tid = threadIdx.x, lane = tid & 31, wid = tid >> 5;

    // phase 1: Ao_e -> smem (3072x16), compute u2 per entry
    for (int i = tid; i < Ff * 16; i += 256) buf[i] = Ao[(size_t)e * Ff * 16 + i];
    __syncthreads();
    for (int i = wid; i < cnt; i += 8) {
        int t = g_ltok[bi * LCAP + i];
        int r = lane & 15, half = lane >> 4;
        const float* hr = g_h + (size_t)t * Ff + half * 1536;
        float acc = 0.f;
        #pragma unroll 4
        for (int d = 0; d < 1536; d += 4) {
            float4 v = *(const float4*)(hr + d);
            int db = (half * 1536 + d) * 16 + r;
            acc += v.x * buf[db] + v.y * buf[db + 16] + v.z * buf[db + 32] + v.w * buf[db + 48];
        }
        acc += __shfl_xor_sync(0xffffffffu, acc, 16);
        if (half == 0) su[i * 16 + r] = acc;
    }
    __syncthreads();

    // phase 2: Bo_e -> smem (16x768), add deltas into out
    for (int i = tid; i < 16 * Dd; i += 256) buf[i] = Bo[(size_t)e * 16 * Dd + i];
    __syncthreads();
    for (int g0i = wid * 4; g0i < cnt; g0i += 32) {
        int nt = cnt - g0i; if (nt > 4) nt = 4;
        float u[4][16]; float gg[4]; int tt[4];
        #pragma unroll
        for (int j = 0; j < 4; j++) {
            int i2 = g0i + (j < nt ? j : 0);
            tt[j] = g_ltok[bi * LCAP + i2];
            gg[j] = (j < nt) ? 2.f * g_lg[bi * LCAP + i2] : 0.f;
            #pragma unroll
            for (int r = 0; r < 16; r++) u[j][r] = su[i2 * 16 + r];
        }
        for (int d = lane; d < Dd; d += 32) {
            float bv[16];
            #pragma unroll
            for (int r = 0; r < 16; r++) bv[r] = buf[r * Dd + d];
            #pragma unroll
            for (int j = 0; j < 4; j++) {
                float dv = 0.f;
                #pragma unroll
                for (int r = 0; r < 16; r++) dv += u[j][r] * bv[r];
                if (gg[j] != 0.f) atomicAdd(out + (size_t)tt[j] * Dd + d, gg[j] * dv);
            }
        }
    }
}

// ---------------- launch ----------------
extern "C" void kernel_launch(void* const* d_in, const int* in_sizes, int n_in,
                              void* d_out, int out_size) {
    const float* x   = (const float*)d_in[0];
    const float* rp  = (const float*)d_in[1];
    const float* lnw = (const float*)d_in[2];
    const float* Wg  = (const float*)d_in[3];
    const float* Wi  = (const float*)d_in[4];
    const float* Wo  = (const float*)d_in[5];
    const float* Ai  = (const float*)d_in[6];
    const float* Bi  = (const float*)d_in[7];
    const float* Ao  = (const float*)d_in[8];
    const float* Bo  = (const float*)d_in[9];
    float* out = (float*)d_out;

    cudaFuncSetAttribute(k_tc_gemm, cudaFuncAttributeMaxDynamicSharedMemorySize, SMEM_GEMM);
    cudaFuncSetAttribute(k_fused1, cudaFuncAttributeMaxDynamicSharedMemorySize, FUSED_SMEM);
    cudaFuncSetAttribute(k_fused2, cudaFuncAttributeMaxDynamicSharedMemorySize, FUSED_SMEM);

    __nv_bfloat16 *A1p, *B1p, *A2p, *B2p;
    float *hp;
    cudaGetSymbolAddress((void**)&A1p, g_A1);
    cudaGetSymbolAddress((void**)&B1p, g_B1);
    cudaGetSymbolAddress((void**)&A2p, g_A2);
    cudaGetSymbolAddress((void**)&B2p, g_B2);
    cudaGetSymbolAddress((void**)&hp, g_h);

    k_init<<<1, 128>>>();
    k_rms<<<Tn, 256>>>(x, lnw);
    k_splitB1<<<Ff, 256>>>(Wi);
    k_splitB2<<<Dd, 256>>>(Wo);
    k_logits<<<Tn / 16, 256>>>(Wg, out);
    k_gate<<<Tn / 256, 256>>>(rp, out);
    k_scan<<<Bbat, 32>>>(out);
    k_aux<<<1, 128>>>(out);

    // GEMM1: h = epi(wi_in @ Wi^T)   [16384 x 3072], K=768, 36 chunks
    k_tc_gemm<<<dim3(Ff / 256, Tn / 128), 512, SMEM_GEMM>>>(A1p, B1p, hp, Ff, Dd, Dd / 64, 3 * Dd / 64, 1, nullptr);
    k_fused1<<<Bbat * Ee, 256, FUSED_SMEM>>>(Ai, Bi);
    k_hC<<<Tn, 256>>>();
    // GEMM2: out = x + (1+gs)*(h @ Wo^T)   [16384 x 768], K=3072, 144 chunks
    k_tc_gemm<<<dim3(Dd / 256, Tn / 128), 512, SMEM_GEMM>>>(A2p, B2p, out, Dd, Ff, Ff / 64, 3 * Ff / 64, 2, x);
    k_fused2<<<Bbat * Ee, 256, FUSED_SMEM>>>(Ao, Bo, out);
}